// round 6
// baseline (speedup 1.0000x reference)
#include <cuda_runtime.h>
#include <cuda_bf16.h>

// Problem: T=64, B(SEQ)=128, IN=256, H=512, G4=2048, NC=10
// Inputs: 0:x 1:w_ih0 2:w_hh0 3:b_ih0 4:b_hh0 5:w_ih1 6:w_hh1 7:b_ih1 8:b_hh1 9:w1 10:b1 11:w2 12:b2

// ------------- scratch (__device__ globals; zero-initialized .bss) -------------
__device__ float g_xg0[64 * 128 * 2048];   // layer0 input-gate precompute, gate-interleaved
__device__ float g_seq0[64 * 128 * 512];   // layer0 hidden sequence
__device__ float g_seq1[64 * 128 * 512];   // layer1 hidden sequence
__device__ float g_c0[128 * 512];
__device__ float g_c1[128 * 512];
__device__ float g_zero[128 * 512];        // never written -> stays zero
__device__ float g_hsplit[32 * 64 * 512];  // split-K partials for head GEMM
__device__ float g_hmid[64 * 512];

// ------------- bf16x3 helpers -------------
__device__ __forceinline__ unsigned pk2(__nv_bfloat16 a, __nv_bfloat16 b) {
    return (unsigned)__bfloat16_as_ushort(a) | ((unsigned)__bfloat16_as_ushort(b) << 16);
}
__device__ __forceinline__ void cvt2(float x0, float x1, unsigned& hi, unsigned& lo) {
    __nv_bfloat16 h0 = __float2bfloat16(x0), h1 = __float2bfloat16(x1);
    hi = pk2(h0, h1);
    lo = pk2(__float2bfloat16(x0 - __bfloat162float(h0)),
             __float2bfloat16(x1 - __bfloat162float(h1)));
}
__device__ __forceinline__ void mma16816(float* c, const unsigned* a, const unsigned* b) {
    asm volatile(
        "mma.sync.aligned.m16n8k16.row.col.f32.bf16.bf16.f32 "
        "{%0,%1,%2,%3},{%4,%5,%6,%7},{%8,%9},{%0,%1,%2,%3};\n"
        : "+f"(c[0]), "+f"(c[1]), "+f"(c[2]), "+f"(c[3])
        : "r"(a[0]), "r"(a[1]), "r"(a[2]), "r"(a[3]), "r"(b[0]), "r"(b[1]));
}

// Tile config: BM=64, BN=32, BK=32, 128 threads (4 warps, each m16 x full n32).
// smem stores packed bf16 pairs, row stride 17 u32 (16 pairs + pad).

__device__ __forceinline__ void fillA(unsigned* sAh, unsigned* sAl,
                                      const float* __restrict__ Ap, size_t lda, int tid) {
#pragma unroll
    for (int j = 0; j < 4; j++) {
        int slot = tid + 128 * j;
        int r = slot >> 3, c = (slot & 7) * 4;
        float4 v = *reinterpret_cast<const float4*>(Ap + (size_t)r * lda + c);
        unsigned h0, l0, h1, l1;
        cvt2(v.x, v.y, h0, l0);
        cvt2(v.z, v.w, h1, l1);
        int base = r * 17 + (c >> 1);
        sAh[base] = h0; sAl[base] = l0;
        sAh[base + 1] = h1; sAl[base + 1] = l1;
    }
}

template <bool IL>
__device__ __forceinline__ void fillB(unsigned* sBh, unsigned* sBl, const float* __restrict__ W,
                                      size_t ldw, int kofs, int n0, int tid) {
#pragma unroll
    for (int j = 0; j < 2; j++) {
        int slot = tid + 128 * j;
        int r = slot >> 3, c = (slot & 7) * 4;
        int nl = n0 + r;
        int nrow = IL ? ((nl & 3) * 512 + (nl >> 2)) : nl;
        float4 v = *reinterpret_cast<const float4*>(W + (size_t)nrow * ldw + kofs + c);
        unsigned h0, l0, h1, l1;
        cvt2(v.x, v.y, h0, l0);
        cvt2(v.z, v.w, h1, l1);
        int base = r * 17 + (c >> 1);
        sBh[base] = h0; sBl[base] = l0;
        sBh[base + 1] = h1; sBl[base + 1] = l1;
    }
}

__device__ __forceinline__ void mma_chunk(float acc[4][4], const unsigned* sAh, const unsigned* sAl,
                                          const unsigned* sBh, const unsigned* sBl,
                                          int wid, int lane) {
    int r0 = wid * 16 + (lane >> 2);
    int qa = lane & 3;
#pragma unroll
    for (int ko = 0; ko < 2; ko++) {
        int kb = ko * 8 + qa;
        unsigned ah[4], al[4];
        ah[0] = sAh[r0 * 17 + kb];       ah[1] = sAh[(r0 + 8) * 17 + kb];
        ah[2] = sAh[r0 * 17 + kb + 4];   ah[3] = sAh[(r0 + 8) * 17 + kb + 4];
        al[0] = sAl[r0 * 17 + kb];       al[1] = sAl[(r0 + 8) * 17 + kb];
        al[2] = sAl[r0 * 17 + kb + 4];   al[3] = sAl[(r0 + 8) * 17 + kb + 4];
#pragma unroll
        for (int j = 0; j < 4; j++) {
            int nr = j * 8 + (lane >> 2);
            unsigned bh[2] = {sBh[nr * 17 + kb], sBh[nr * 17 + kb + 4]};
            unsigned bl[2] = {sBl[nr * 17 + kb], sBl[nr * 17 + kb + 4]};
            mma16816(acc[j], ah, bh);   // hi*hi
            mma16816(acc[j], ah, bl);   // hi*lo
            mma16816(acc[j], al, bh);   // lo*hi
        }
    }
}

__device__ __forceinline__ void store_acc(float* Csh, float acc[4][4], int wid, int lane) {
    int r = wid * 16 + (lane >> 2);
    int c0 = (lane & 3) * 2;
#pragma unroll
    for (int j = 0; j < 4; j++) {
        int c = j * 8 + c0;
        Csh[r * 32 + c] = acc[j][0];
        Csh[r * 32 + c + 1] = acc[j][1];
        Csh[(r + 8) * 32 + c] = acc[j][2];
        Csh[(r + 8) * 32 + c + 1] = acc[j][3];
    }
}

// ================= generic GEMM: C = A @ W^T (+bias), optional interleaved cols, split-K =================
// SRC: 0 = param A, 1 = g_seq1.  DST: 0 = g_xg0, 1 = g_hsplit.
template <bool IL, bool BIAS, int SRC, int DST>
__global__ void __launch_bounds__(128) gemm_k(const float* __restrict__ Ain, int lda,
                                              const float* __restrict__ W, int ldw,
                                              const float* __restrict__ bias_a,
                                              const float* __restrict__ bias_b,
                                              int ldc, int kchunk, int mslice) {
    __shared__ unsigned sA[2 * 64 * 17];
    __shared__ unsigned sB[2 * 32 * 17];
    unsigned *sAh = sA, *sAl = sA + 64 * 17, *sBh = sB, *sBl = sB + 32 * 17;
    int tid = threadIdx.x, wid = tid >> 5, lane = tid & 31;
    int n0 = blockIdx.x * 32, m0 = blockIdx.y * 64;
    const float* A = (SRC == 0) ? Ain : g_seq1;
    float* C = ((DST == 0) ? g_xg0 : g_hsplit) + (size_t)blockIdx.z * mslice;
    int k0s = blockIdx.z * kchunk;

    float acc[4][4];
#pragma unroll
    for (int j = 0; j < 4; j++)
#pragma unroll
        for (int q = 0; q < 4; q++) acc[j][q] = 0.f;

    const float* Ap0 = A + (size_t)m0 * lda;
    for (int k0 = k0s; k0 < k0s + kchunk; k0 += 32) {
        fillA(sAh, sAl, Ap0 + k0, lda, tid);
        fillB<IL>(sBh, sBl, W, ldw, k0, n0, tid);
        __syncthreads();
        mma_chunk(acc, sAh, sAl, sBh, sBl, wid, lane);
        __syncthreads();
    }
    float* Csh = (float*)sA;
    store_acc(Csh, acc, wid, lane);
    __syncthreads();
    for (int p = tid; p < 2048; p += 128) {
        int r = p >> 5, cl = p & 31;
        int gcol = n0 + cl;
        float v = Csh[p];
        if (BIAS) {
            int nlin = (gcol & 3) * 512 + (gcol >> 2);
            v += bias_a[nlin] + bias_b[nlin];
        }
        C[(size_t)(m0 + r) * ldc + gcol] = v;
    }
}

// ================= LSTM superstep: layer0 step t=s and layer1 step t=s-1 in one launch =================
__global__ void __launch_bounds__(128) lstm_step(int s, const float* __restrict__ w_hh0,
                                                 const float* __restrict__ w_ih1,
                                                 const float* __restrict__ w_hh1,
                                                 const float* __restrict__ b_ih1,
                                                 const float* __restrict__ b_hh1) {
    int layer = blockIdx.z;
    if (layer == 0) { if (s >= 64) return; }
    else            { if (s < 1)  return; }
    int t = s - layer;

    __shared__ unsigned sA[2 * 64 * 17];
    __shared__ unsigned sB[2 * 32 * 17];
    unsigned *sAh = sA, *sAl = sA + 64 * 17, *sBh = sB, *sBl = sB + 32 * 17;
    int tid = threadIdx.x, wid = tid >> 5, lane = tid & 31;
    int n0 = blockIdx.x * 32, m0 = blockIdx.y * 64;

    const float* seqA = (layer == 0) ? g_seq0 : g_seq1;
    const float* hprev = (t == 0) ? g_zero : seqA + (size_t)(t - 1) * 65536;
    const float* cprev = (t == 0) ? g_zero : ((layer == 0) ? g_c0 : g_c1);
    float* cnew = (layer == 0) ? g_c0 : g_c1;
    float* hnew = ((layer == 0) ? g_seq0 : g_seq1) + (size_t)t * 65536;
    const float* x1 = g_seq0 + (size_t)t * 65536;  // layer1 concat first half
    int K = layer ? 1024 : 512;

    float acc[4][4];
#pragma unroll
    for (int j = 0; j < 4; j++)
#pragma unroll
        for (int q = 0; q < 4; q++) acc[j][q] = 0.f;

    for (int k0 = 0; k0 < K; k0 += 32) {
        const float* Ab; int kc;
        if (layer == 1 && k0 < 512) { Ab = x1; kc = k0; }
        else { Ab = hprev; kc = k0 - (layer ? 512 : 0); }
        fillA(sAh, sAl, Ab + (size_t)m0 * 512 + kc, 512, tid);

        const float* Wb; int kw;
        if (layer == 0) { Wb = w_hh0; kw = k0; }
        else if (k0 < 512) { Wb = w_ih1; kw = k0; }
        else { Wb = w_hh1; kw = k0 - 512; }
        fillB<true>(sBh, sBl, Wb, 512, kw, n0, tid);

        __syncthreads();
        mma_chunk(acc, sAh, sAl, sBh, sBl, wid, lane);
        __syncthreads();
    }

    float* Csh = (float*)sA;
    store_acc(Csh, acc, wid, lane);
    __syncthreads();

    int h0 = n0 >> 2;
    for (int p = tid; p < 512; p += 128) {
        int bl = p >> 3, hl = p & 7;
        int cb = bl * 32 + hl * 4;
        float gi = Csh[cb], gf = Csh[cb + 1], gg = Csh[cb + 2], go = Csh[cb + 3];
        int b = m0 + bl, h = h0 + hl;
        if (layer == 0) {
            const float* xr = g_xg0 + ((size_t)t * 128 + b) * 2048 + n0 + hl * 4;
            gi += xr[0]; gf += xr[1]; gg += xr[2]; go += xr[3];
        } else {
            gi += b_ih1[h] + b_hh1[h];
            gf += b_ih1[512 + h] + b_hh1[512 + h];
            gg += b_ih1[1024 + h] + b_hh1[1024 + h];
            go += b_ih1[1536 + h] + b_hh1[1536 + h];
        }
        float ii = 1.f / (1.f + __expf(-gi));
        float ff = 1.f / (1.f + __expf(-gf));
        float g2 = tanhf(gg);
        float oo = 1.f / (1.f + __expf(-go));
        float c = ff * cprev[b * 512 + h] + ii * g2;
        cnew[b * 512 + h] = c;
        hnew[(size_t)b * 512 + h] = oo * tanhf(c);
    }
}

// ================= head epilogue =================
__global__ void head_reduce(const float* __restrict__ b1) {
    int t = blockIdx.x;
    for (int n = threadIdx.x; n < 512; n += blockDim.x) {
        float s = 0.f;
#pragma unroll
        for (int z = 0; z < 32; z++) s += g_hsplit[z * 32768 + t * 512 + n];
        s += b1[n];
        g_hmid[t * 512 + n] = s > 0.f ? s : 0.f;
    }
}

__global__ void head_final(const float* __restrict__ w2, const float* __restrict__ b2,
                           float* __restrict__ out) {
    int t = blockIdx.x, nc = blockIdx.y, lane = threadIdx.x;
    float s = 0.f;
    for (int k = lane; k < 512; k += 32) s += g_hmid[t * 512 + k] * w2[nc * 512 + k];
#pragma unroll
    for (int o = 16; o; o >>= 1) s += __shfl_xor_sync(0xFFFFFFFFu, s, o);
    if (lane == 0) out[t * 10 + nc] = s + b2[nc];
}

// ================= launch =================
extern "C" void kernel_launch(void* const* d_in, const int* in_sizes, int n_in,
                              void* d_out, int out_size) {
    const float* x     = (const float*)d_in[0];
    const float* w_ih0 = (const float*)d_in[1];
    const float* w_hh0 = (const float*)d_in[2];
    const float* b_ih0 = (const float*)d_in[3];
    const float* b_hh0 = (const float*)d_in[4];
    const float* w_ih1 = (const float*)d_in[5];
    const float* w_hh1 = (const float*)d_in[6];
    const float* b_ih1 = (const float*)d_in[7];
    const float* b_hh1 = (const float*)d_in[8];
    const float* w1    = (const float*)d_in[9];
    const float* b1    = (const float*)d_in[10];
    const float* w2    = (const float*)d_in[11];
    const float* b2    = (const float*)d_in[12];
    float* out = (float*)d_out;
    (void)in_sizes; (void)n_in; (void)out_size;

    // Phase A: xg0 = x @ w_ih0^T + b_ih0 + b_hh0 (gate-interleaved columns)
    gemm_k<true, true, 0, 0><<<dim3(64, 128, 1), 128>>>(x, 256, w_ih0, 256, b_ih0, b_hh0,
                                                        2048, 256, 0);
    // Diagonal-pipelined recurrence: 65 supersteps
    for (int s = 0; s <= 64; s++) {
        lstm_step<<<dim3(64, 2, 2), 128>>>(s, w_hh0, w_ih1, w_hh1, b_ih1, b_hh1);
    }
    // Head GEMM: hsplit[z] = seq1 @ w1^T (K split into 32 chunks of 2048)
    gemm_k<false, false, 1, 1><<<dim3(16, 1, 32), 128>>>(nullptr, 65536, w1, 65536,
                                                         nullptr, nullptr, 512, 2048, 64 * 512);
    head_reduce<<<64, 256>>>(b1);
    head_final<<<dim3(64, 10), 32>>>(w2, b2, out);
}

// round 7
// speedup vs baseline: 1.7961x; 1.7961x over previous
#include <cuda_runtime.h>
#include <cuda_bf16.h>

// Problem: T=64, B(SEQ)=128, IN=256, H=512, G4=2048, NC=10
// Inputs: 0:x 1:w_ih0 2:w_hh0 3:b_ih0 4:b_hh0 5:w_ih1 6:w_hh1 7:b_ih1 8:b_hh1 9:w1 10:b1 11:w2 12:b2

// ------------- scratch (__device__ globals; zero-initialized .bss) -------------
__device__ float g_xg0[64 * 128 * 2048];   // layer0 input-gate precompute, gate-interleaved
__device__ float g_seq1[64 * 128 * 512];   // layer1 hidden sequence fp32 (head GEMM input)
__device__ float g_c0[128 * 512];
__device__ float g_c1[128 * 512];
__device__ float g_zero[128 * 512];        // never written -> stays zero
__device__ float g_hsplit[32 * 64 * 512];  // split-K partials for head GEMM
__device__ float g_hmid[64 * 512];

// packed bf16 hi/lo planes (weights packed once per launch; h packed by epilogues)
__device__ __nv_bfloat16 g_w0hi[2048 * 512],  g_w0lo[2048 * 512];
__device__ __nv_bfloat16 g_w1hi[2048 * 1024], g_w1lo[2048 * 1024];
__device__ __nv_bfloat16 g_s0hi[64 * 128 * 512], g_s0lo[64 * 128 * 512];
__device__ __nv_bfloat16 g_s1hi[64 * 128 * 512], g_s1lo[64 * 128 * 512];
__device__ __nv_bfloat16 g_zph[128 * 512], g_zpl[128 * 512];  // never written -> zero

// ------------- bf16x3 helpers -------------
__device__ __forceinline__ unsigned pk2(__nv_bfloat16 a, __nv_bfloat16 b) {
    return (unsigned)__bfloat16_as_ushort(a) | ((unsigned)__bfloat16_as_ushort(b) << 16);
}
__device__ __forceinline__ void cvt2(float x0, float x1, unsigned& hi, unsigned& lo) {
    __nv_bfloat16 h0 = __float2bfloat16(x0), h1 = __float2bfloat16(x1);
    hi = pk2(h0, h1);
    lo = pk2(__float2bfloat16(x0 - __bfloat162float(h0)),
             __float2bfloat16(x1 - __bfloat162float(h1)));
}
__device__ __forceinline__ void mma16816(float* c, const unsigned* a, const unsigned* b) {
    asm volatile(
        "mma.sync.aligned.m16n8k16.row.col.f32.bf16.bf16.f32 "
        "{%0,%1,%2,%3},{%4,%5,%6,%7},{%8,%9},{%0,%1,%2,%3};\n"
        : "+f"(c[0]), "+f"(c[1]), "+f"(c[2]), "+f"(c[3])
        : "r"(a[0]), "r"(a[1]), "r"(a[2]), "r"(a[3]), "r"(b[0]), "r"(b[1]));
}
__device__ __forceinline__ void ldsm4(unsigned& r0, unsigned& r1, unsigned& r2, unsigned& r3,
                                      unsigned addr) {
    asm volatile("ldmatrix.sync.aligned.m8n8.x4.shared.b16 {%0,%1,%2,%3}, [%4];\n"
                 : "=r"(r0), "=r"(r1), "=r"(r2), "=r"(r3) : "r"(addr));
}
__device__ __forceinline__ void cpa16(unsigned* dst, const void* src) {
    unsigned d = (unsigned)__cvta_generic_to_shared(dst);
    asm volatile("cp.async.cg.shared.global [%0], [%1], 16;\n" :: "r"(d), "l"(src));
}

// ================= weight pre-pack (gate-interleaved, bf16 hi/lo split) =================
__global__ void pack_w0k(const float* __restrict__ w) {
    int i = blockIdx.x * 256 + threadIdx.x;             // 2048*512 total
    int nl = i >> 9, k = i & 511;
    float v = w[(size_t)((nl & 3) * 512 + (nl >> 2)) * 512 + k];
    __nv_bfloat16 h = __float2bfloat16(v);
    g_w0hi[i] = h;
    g_w0lo[i] = __float2bfloat16(v - __bfloat162float(h));
}
__global__ void pack_w1k(const float* __restrict__ wi, const float* __restrict__ wh) {
    int i = blockIdx.x * 256 + threadIdx.x;             // 2048*1024 total
    int nl = i >> 10, k = i & 1023;
    int orow = (nl & 3) * 512 + (nl >> 2);
    float v = (k < 512) ? wi[(size_t)orow * 512 + k] : wh[(size_t)orow * 512 + k - 512];
    __nv_bfloat16 h = __float2bfloat16(v);
    g_w1hi[i] = h;
    g_w1lo[i] = __float2bfloat16(v - __bfloat162float(h));
}

// ================= LSTM superstep kernel (pipelined, BM=128 BN=32 BK=64, 256 thr) ========
// smem stage (u32): [Ahi 4608][Alo 4608][Bhi 1152][Blo 1152] = 11520 u32; 2 stages = 92160 B
// row stride 36 u32 (144B, 16B-aligned, conflict-free for ldmatrix)
__device__ __forceinline__ void ld_stage(unsigned* st,
                                         const __nv_bfloat16* Ah, const __nv_bfloat16* Al, int ak,
                                         const __nv_bfloat16* Wh, const __nv_bfloat16* Wl, int wk,
                                         int wld, int n0, int tid) {
#pragma unroll
    for (int j = 0; j < 4; j++) {
        int slot = tid + (j << 8);
        int r = slot >> 3, sg = (slot & 7) << 3;        // sg: bf16 elems (8 = 16B)
        size_t go = (size_t)r * 512 + ak + sg;
        int so = r * 36 + (sg >> 1);
        cpa16(st + so, Ah + go);
        cpa16(st + 4608 + so, Al + go);
    }
    {
        int r = tid >> 3, sg = (tid & 7) << 3;
        size_t go = (size_t)(n0 + r) * wld + wk + sg;
        int so = r * 36 + (sg >> 1);
        cpa16(st + 9216 + so, Wh + go);
        cpa16(st + 10368 + so, Wl + go);
    }
}

__global__ void __launch_bounds__(256, 1) lstm_step2(int s, const float* __restrict__ b_ih1,
                                                     const float* __restrict__ b_hh1) {
    extern __shared__ unsigned sm[];
    int layer = blockIdx.y;
    if (layer == 0) { if (s >= 64) return; } else { if (s < 1) return; }
    int t = s - layer;
    int tid = threadIdx.x, lane = tid & 31, wid = tid >> 5;
    int wm = wid >> 1, wn = wid & 1;
    int n0 = blockIdx.x * 32;
    int nch = layer ? 16 : 8;

    const __nv_bfloat16 *Wh, *Wl; int wld;
    if (layer == 0) { Wh = g_w0hi; Wl = g_w0lo; wld = 512; }
    else            { Wh = g_w1hi; Wl = g_w1lo; wld = 1024; }

    const __nv_bfloat16 *Hh, *Hl;   // h_prev plane of this layer
    if (t == 0) { Hh = g_zph; Hl = g_zpl; }
    else {
        size_t o = (size_t)(t - 1) * 65536;
        if (layer == 0) { Hh = g_s0hi + o; Hl = g_s0lo + o; }
        else            { Hh = g_s1hi + o; Hl = g_s1lo + o; }
    }
    const __nv_bfloat16* Xh = g_s0hi + (size_t)t * 65536;  // layer1 concat first half
    const __nv_bfloat16* Xl = g_s0lo + (size_t)t * 65536;

    // prefetch chunk 0
    {
        const __nv_bfloat16* Ah = layer ? Xh : Hh;
        const __nv_bfloat16* Al = layer ? Xl : Hl;
        ld_stage(sm, Ah, Al, 0, Wh, Wl, 0, wld, n0, tid);
    }
    asm volatile("cp.async.commit_group;\n");

    // ldmatrix per-lane base byte-offsets within a stage
    unsigned aoff[2], boff;
    {
        int tl = lane >> 3, trw = lane & 7;
#pragma unroll
        for (int mt = 0; mt < 2; mt++) {
            int row = wm * 32 + mt * 16 + (tl & 1) * 8 + trw;
            aoff[mt] = (unsigned)(row * 36 + (tl >> 1) * 4) * 4u;
        }
        int brow = wn * 16 + (tl >> 1) * 8 + trw;
        boff = (unsigned)(brow * 36 + (tl & 1) * 4) * 4u;
    }
    unsigned smbase = (unsigned)__cvta_generic_to_shared(sm);

    float acc[2][2][4];
#pragma unroll
    for (int a = 0; a < 2; a++)
#pragma unroll
        for (int b = 0; b < 2; b++)
#pragma unroll
            for (int q = 0; q < 4; q++) acc[a][b][q] = 0.f;

    for (int ch = 0; ch < nch; ch++) {
        if (ch + 1 < nch) {
            int k0 = (ch + 1) << 6;
            const __nv_bfloat16 *Ah, *Al; int ak;
            if (layer && k0 < 512) { Ah = Xh; Al = Xl; ak = k0; }
            else { Ah = Hh; Al = Hl; ak = layer ? (k0 - 512) : k0; }
            ld_stage(sm + ((ch + 1) & 1) * 11520, Ah, Al, ak, Wh, Wl, k0, wld, n0, tid);
            asm volatile("cp.async.commit_group;\n");
            asm volatile("cp.async.wait_group 1;\n");
        } else {
            asm volatile("cp.async.wait_group 0;\n");
        }
        __syncthreads();
        unsigned sb = smbase + ((ch & 1) ? 46080u : 0u);
#pragma unroll
        for (int ks = 0; ks < 4; ks++) {
            unsigned kb = (unsigned)ks * 32u;
            unsigned ah[2][4], al[2][4], bh[4], bl[4];
#pragma unroll
            for (int mt = 0; mt < 2; mt++) {
                ldsm4(ah[mt][0], ah[mt][1], ah[mt][2], ah[mt][3], sb + aoff[mt] + kb);
                ldsm4(al[mt][0], al[mt][1], al[mt][2], al[mt][3], sb + 18432u + aoff[mt] + kb);
            }
            ldsm4(bh[0], bh[1], bh[2], bh[3], sb + 36864u + boff + kb);
            ldsm4(bl[0], bl[1], bl[2], bl[3], sb + 41472u + boff + kb);
#pragma unroll
            for (int mt = 0; mt < 2; mt++)
#pragma unroll
                for (int nt = 0; nt < 2; nt++) {
                    mma16816(acc[mt][nt], ah[mt], bh + nt * 2);
                    mma16816(acc[mt][nt], ah[mt], bl + nt * 2);
                    mma16816(acc[mt][nt], al[mt], bh + nt * 2);
                }
        }
        __syncthreads();
    }

    // ---- epilogue: gates -> cell -> h (fp32 + packed bf16 hi/lo) ----
    float* Csh = (float*)sm;   // 128 x 32, stride 33 (16.9 KB, reuses stage0)
    {
        int g2 = lane >> 2, q2 = (lane & 3) * 2;
#pragma unroll
        for (int mt = 0; mt < 2; mt++)
#pragma unroll
            for (int nt = 0; nt < 2; nt++) {
                int r = wm * 32 + mt * 16 + g2;
                int c = wn * 16 + nt * 8 + q2;
                Csh[r * 33 + c]           = acc[mt][nt][0];
                Csh[r * 33 + c + 1]       = acc[mt][nt][1];
                Csh[(r + 8) * 33 + c]     = acc[mt][nt][2];
                Csh[(r + 8) * 33 + c + 1] = acc[mt][nt][3];
            }
    }
    __syncthreads();

    const float* cprev = (t == 0) ? g_zero : (layer ? g_c1 : g_c0);
    float* cnew = layer ? g_c1 : g_c0;
    size_t to = (size_t)t * 65536;
    __nv_bfloat16* ohi = (layer ? g_s1hi : g_s0hi) + to;
    __nv_bfloat16* olo = (layer ? g_s1lo : g_s0lo) + to;
    int h0 = n0 >> 2;
#pragma unroll
    for (int it = 0; it < 4; it++) {
        int p = tid + (it << 8);
        int b = p >> 3, hl = p & 7;
        float gi = Csh[b * 33 + hl * 4 + 0];
        float gf = Csh[b * 33 + hl * 4 + 1];
        float gg = Csh[b * 33 + hl * 4 + 2];
        float go = Csh[b * 33 + hl * 4 + 3];
        int h = h0 + hl;
        if (layer == 0) {
            const float4 xr = *reinterpret_cast<const float4*>(
                g_xg0 + ((size_t)t * 128 + b) * 2048 + n0 + hl * 4);
            gi += xr.x; gf += xr.y; gg += xr.z; go += xr.w;
        } else {
            gi += b_ih1[h] + b_hh1[h];
            gf += b_ih1[512 + h] + b_hh1[512 + h];
            gg += b_ih1[1024 + h] + b_hh1[1024 + h];
            go += b_ih1[1536 + h] + b_hh1[1536 + h];
        }
        float ii = 1.f / (1.f + __expf(-gi));
        float ff = 1.f / (1.f + __expf(-gf));
        float g2v = tanhf(gg);
        float oo = 1.f / (1.f + __expf(-go));
        float c = ff * cprev[b * 512 + h] + ii * g2v;
        cnew[b * 512 + h] = c;
        float hv = oo * tanhf(c);
        __nv_bfloat16 hb = __float2bfloat16(hv);
        ohi[b * 512 + h] = hb;
        olo[b * 512 + h] = __float2bfloat16(hv - __bfloat162float(hb));
        if (layer) g_seq1[to + b * 512 + h] = hv;
    }
}

// ================= phase-A / head GEMM (old style; adequate for now) =================
__device__ __forceinline__ void fillA(unsigned* sAh, unsigned* sAl,
                                      const float* __restrict__ Ap, size_t lda, int tid) {
#pragma unroll
    for (int j = 0; j < 4; j++) {
        int slot = tid + 128 * j;
        int r = slot >> 3, c = (slot & 7) * 4;
        float4 v = *reinterpret_cast<const float4*>(Ap + (size_t)r * lda + c);
        unsigned h0, l0, h1, l1;
        cvt2(v.x, v.y, h0, l0);
        cvt2(v.z, v.w, h1, l1);
        int base = r * 17 + (c >> 1);
        sAh[base] = h0; sAl[base] = l0;
        sAh[base + 1] = h1; sAl[base + 1] = l1;
    }
}
template <bool IL>
__device__ __forceinline__ void fillB(unsigned* sBh, unsigned* sBl, const float* __restrict__ W,
                                      size_t ldw, int kofs, int n0, int tid) {
#pragma unroll
    for (int j = 0; j < 2; j++) {
        int slot = tid + 128 * j;
        int r = slot >> 3, c = (slot & 7) * 4;
        int nl = n0 + r;
        int nrow = IL ? ((nl & 3) * 512 + (nl >> 2)) : nl;
        float4 v = *reinterpret_cast<const float4*>(W + (size_t)nrow * ldw + kofs + c);
        unsigned h0, l0, h1, l1;
        cvt2(v.x, v.y, h0, l0);
        cvt2(v.z, v.w, h1, l1);
        int base = r * 17 + (c >> 1);
        sBh[base] = h0; sBl[base] = l0;
        sBh[base + 1] = h1; sBl[base + 1] = l1;
    }
}
__device__ __forceinline__ void mma_chunk(float acc[4][4], const unsigned* sAh, const unsigned* sAl,
                                          const unsigned* sBh, const unsigned* sBl,
                                          int wid, int lane) {
    int r0 = wid * 16 + (lane >> 2);
    int qa = lane & 3;
#pragma unroll
    for (int ko = 0; ko < 2; ko++) {
        int kb = ko * 8 + qa;
        unsigned ah[4], al[4];
        ah[0] = sAh[r0 * 17 + kb];       ah[1] = sAh[(r0 + 8) * 17 + kb];
        ah[2] = sAh[r0 * 17 + kb + 4];   ah[3] = sAh[(r0 + 8) * 17 + kb + 4];
        al[0] = sAl[r0 * 17 + kb];       al[1] = sAl[(r0 + 8) * 17 + kb];
        al[2] = sAl[r0 * 17 + kb + 4];   al[3] = sAl[(r0 + 8) * 17 + kb + 4];
#pragma unroll
        for (int j = 0; j < 4; j++) {
            int nr = j * 8 + (lane >> 2);
            unsigned bh[2] = {sBh[nr * 17 + kb], sBh[nr * 17 + kb + 4]};
            unsigned bl[2] = {sBl[nr * 17 + kb], sBl[nr * 17 + kb + 4]};
            mma16816(acc[j], ah, bh);
            mma16816(acc[j], ah, bl);
            mma16816(acc[j], al, bh);
        }
    }
}
__device__ __forceinline__ void store_acc(float* Csh, float acc[4][4], int wid, int lane) {
    int r = wid * 16 + (lane >> 2);
    int c0 = (lane & 3) * 2;
#pragma unroll
    for (int j = 0; j < 4; j++) {
        int c = j * 8 + c0;
        Csh[r * 32 + c] = acc[j][0];
        Csh[r * 32 + c + 1] = acc[j][1];
        Csh[(r + 8) * 32 + c] = acc[j][2];
        Csh[(r + 8) * 32 + c + 1] = acc[j][3];
    }
}

// SRC: 0 = param A, 1 = g_seq1.  DST: 0 = g_xg0, 1 = g_hsplit.
template <bool IL, bool BIAS, int SRC, int DST>
__global__ void __launch_bounds__(128) gemm_k(const float* __restrict__ Ain, int lda,
                                              const float* __restrict__ W, int ldw,
                                              const float* __restrict__ bias_a,
                                              const float* __restrict__ bias_b,
                                              int ldc, int kchunk, int mslice) {
    __shared__ unsigned sA[2 * 64 * 17];
    __shared__ unsigned sB[2 * 32 * 17];
    unsigned *sAh = sA, *sAl = sA + 64 * 17, *sBh = sB, *sBl = sB + 32 * 17;
    int tid = threadIdx.x, wid = tid >> 5, lane = tid & 31;
    int n0 = blockIdx.x * 32, m0 = blockIdx.y * 64;
    const float* A = (SRC == 0) ? Ain : g_seq1;
    float* C = ((DST == 0) ? g_xg0 : g_hsplit) + (size_t)blockIdx.z * mslice;
    int k0s = blockIdx.z * kchunk;

    float acc[4][4];
#pragma unroll
    for (int j = 0; j < 4; j++)
#pragma unroll
        for (int q = 0; q < 4; q++) acc[j][q] = 0.f;

    const float* Ap0 = A + (size_t)m0 * lda;
    for (int k0 = k0s; k0 < k0s + kchunk; k0 += 32) {
        fillA(sAh, sAl, Ap0 + k0, lda, tid);
        fillB<IL>(sBh, sBl, W, ldw, k0, n0, tid);
        __syncthreads();
        mma_chunk(acc, sAh, sAl, sBh, sBl, wid, lane);
        __syncthreads();
    }
    float* Csh = (float*)sA;
    store_acc(Csh, acc, wid, lane);
    __syncthreads();
    for (int p = tid; p < 2048; p += 128) {
        int r = p >> 5, cl = p & 31;
        int gcol = n0 + cl;
        float v = Csh[p];
        if (BIAS) {
            int nlin = (gcol & 3) * 512 + (gcol >> 2);
            v += bias_a[nlin] + bias_b[nlin];
        }
        C[(size_t)(m0 + r) * ldc + gcol] = v;
    }
}

// ================= head epilogue =================
__global__ void head_reduce(const float* __restrict__ b1) {
    int t = blockIdx.x;
    for (int n = threadIdx.x; n < 512; n += blockDim.x) {
        float s = 0.f;
#pragma unroll
        for (int z = 0; z < 32; z++) s += g_hsplit[z * 32768 + t * 512 + n];
        s += b1[n];
        g_hmid[t * 512 + n] = s > 0.f ? s : 0.f;
    }
}
__global__ void head_final(const float* __restrict__ w2, const float* __restrict__ b2,
                           float* __restrict__ out) {
    int t = blockIdx.x, nc = blockIdx.y, lane = threadIdx.x;
    float s = 0.f;
    for (int k = lane; k < 512; k += 32) s += g_hmid[t * 512 + k] * w2[nc * 512 + k];
#pragma unroll
    for (int o = 16; o; o >>= 1) s += __shfl_xor_sync(0xFFFFFFFFu, s, o);
    if (lane == 0) out[t * 10 + nc] = s + b2[nc];
}

// ================= launch =================
extern "C" void kernel_launch(void* const* d_in, const int* in_sizes, int n_in,
                              void* d_out, int out_size) {
    const float* x     = (const float*)d_in[0];
    const float* w_ih0 = (const float*)d_in[1];
    const float* w_hh0 = (const float*)d_in[2];
    const float* b_ih0 = (const float*)d_in[3];
    const float* b_hh0 = (const float*)d_in[4];
    const float* w_ih1 = (const float*)d_in[5];
    const float* w_hh1 = (const float*)d_in[6];
    const float* b_ih1 = (const float*)d_in[7];
    const float* b_hh1 = (const float*)d_in[8];
    const float* w1    = (const float*)d_in[9];
    const float* b1    = (const float*)d_in[10];
    const float* w2    = (const float*)d_in[11];
    const float* b2    = (const float*)d_in[12];
    float* out = (float*)d_out;
    (void)in_sizes; (void)n_in; (void)out_size;

    cudaFuncSetAttribute(lstm_step2, cudaFuncAttributeMaxDynamicSharedMemorySize, 92160);

    // Weight pre-pack (bf16 hi/lo, gate-interleaved; layer1 = concat [w_ih1;w_hh1])
    pack_w0k<<<4096, 256>>>(w_hh0);
    pack_w1k<<<8192, 256>>>(w_ih1, w_hh1);

    // Phase A: xg0 = x @ w_ih0^T + b_ih0 + b_hh0 (gate-interleaved columns)
    gemm_k<true, true, 0, 0><<<dim3(64, 128, 1), 128>>>(x, 256, w_ih0, 256, b_ih0, b_hh0,
                                                        2048, 256, 0);
    // Diagonal-pipelined recurrence: 65 supersteps
    for (int s = 0; s <= 64; s++) {
        lstm_step2<<<dim3(64, 2), 256, 92160>>>(s, b_ih1, b_hh1);
    }
    // Head GEMM: hsplit[z] = seq1 @ w1^T (K split into 32 chunks of 2048)
    gemm_k<false, false, 1, 1><<<dim3(16, 1, 32), 128>>>(nullptr, 65536, w1, 65536,
                                                         nullptr, nullptr, 512, 2048, 64 * 512);
    head_reduce<<<64, 256>>>(b1);
    head_final<<<dim3(64, 10), 32>>>(w2, b2, out);
}